// round 13
// baseline (speedup 1.0000x reference)
#include <cuda_runtime.h>
#include <cuda_bf16.h>
#include <cstdint>

// ---------------------------------------------------------------------------
// LocalBitPredictor: per-pixel 2-layer MLP over 71 binary 3x3-neighborhood
// bits of an 8-channel binary image.
// Layer 1: int8 IMMA m16n8k32, K=64; W1 ~= 2^-17*(128*a+b), a,b s8; single
//   s32 chain (pass1 A=feat*128 u8, pass2 A=feat); D!=C zero-C first MMA.
// Layer 2: bf16 mma m16n8k16 on relu(I2F(acc)), 2^-17 folded into W2, A
//   hi/lo split; two independent chains ordered ah->ah->al (late operand
//   last); o1 seeded with b2 via D!=C.
// R13: explicit cross-tile software pipeline of the sp LDS loads (prefetch
//   after A-build, drains under the epilogue), PRMT bias fixup.
// ---------------------------------------------------------------------------

#define ZROW 264    // spread-word row stride (256 data + 8 zeroed pad)
#define BQSTRIDE 68 // int8 weight row stride (64 + 4 pad)
#define W2STRIDE 72 // W2 smem row stride (32 bf16 = 64B + 8 pad)

static __device__ __forceinline__ void imma16832(int* c, const uint32_t* a,
                                                 const uint32_t* b) {
  asm volatile(
      "mma.sync.aligned.m16n8k32.row.col.s32.u8.s8.s32 "
      "{%0,%1,%2,%3}, {%4,%5,%6,%7}, {%8,%9}, {%0,%1,%2,%3};"
      : "+r"(c[0]), "+r"(c[1]), "+r"(c[2]), "+r"(c[3])
      : "r"(a[0]), "r"(a[1]), "r"(a[2]), "r"(a[3]), "r"(b[0]), "r"(b[1]));
}

static __device__ __forceinline__ void imma16832_dc(int* d, const uint32_t* a,
                                                    const uint32_t* b,
                                                    const int* c) {
  asm volatile(
      "mma.sync.aligned.m16n8k32.row.col.s32.u8.s8.s32 "
      "{%0,%1,%2,%3}, {%4,%5,%6,%7}, {%8,%9}, {%10,%11,%12,%13};"
      : "=r"(d[0]), "=r"(d[1]), "=r"(d[2]), "=r"(d[3])
      : "r"(a[0]), "r"(a[1]), "r"(a[2]), "r"(a[3]), "r"(b[0]), "r"(b[1]),
        "r"(c[0]), "r"(c[1]), "r"(c[2]), "r"(c[3]));
}

static __device__ __forceinline__ void mma16816(float* c, const uint32_t* a,
                                                const uint32_t* b) {
  asm volatile(
      "mma.sync.aligned.m16n8k16.row.col.f32.bf16.bf16.f32 "
      "{%0,%1,%2,%3}, {%4,%5,%6,%7}, {%8,%9}, {%0,%1,%2,%3};"
      : "+f"(c[0]), "+f"(c[1]), "+f"(c[2]), "+f"(c[3])
      : "r"(a[0]), "r"(a[1]), "r"(a[2]), "r"(a[3]), "r"(b[0]), "r"(b[1]));
}

static __device__ __forceinline__ void mma16816_dc(float* d, const uint32_t* a,
                                                   const uint32_t* b,
                                                   const float* c) {
  asm volatile(
      "mma.sync.aligned.m16n8k16.row.col.f32.bf16.bf16.f32 "
      "{%0,%1,%2,%3}, {%4,%5,%6,%7}, {%8,%9}, {%10,%11,%12,%13};"
      : "=f"(d[0]), "=f"(d[1]), "=f"(d[2]), "=f"(d[3])
      : "r"(a[0]), "r"(a[1]), "r"(a[2]), "r"(a[3]), "r"(b[0]), "r"(b[1]),
        "f"(c[0]), "f"(c[1]), "f"(c[2]), "f"(c[3]));
}

static __device__ __forceinline__ uint32_t pack_bf16(float lo, float hi) {
  uint32_t r;
  asm("cvt.rn.bf16x2.f32 %0, %1, %2;" : "=r"(r) : "f"(hi), "f"(lo));
  return r;
}

static __device__ __forceinline__ uint32_t resid_pack(uint32_t h, float lo,
                                                      float hi) {
  float hlo = __uint_as_float(h << 16);
  float hhi = __uint_as_float(h & 0xFFFF0000u);
  return pack_bf16(lo - hlo, hi - hhi);
}

// 3-FFMA nibble dot (exact: z in {0,1}, nib <= 15) -> spread to byte lanes
static __device__ __forceinline__ uint32_t spread4(float a, float b, float c,
                                                   float d) {
  float f = fmaf(b, 2.0f, a);
  f = fmaf(c, 4.0f, f);
  f = fmaf(d, 8.0f, f);
  unsigned nib = (unsigned)f;
  return (nib * 0x00204081u) & 0x01010101u;
}

__global__ void __launch_bounds__(256, 3)
lbp_kernel(const float* __restrict__ z, const float* __restrict__ W1,
           const float* __restrict__ b1, const float* __restrict__ W2,
           const float* __restrict__ b2, float* __restrict__ out) {
  // 4-word front pad (zeroed) + 10 rows; rows 16B-aligned at data base +4
  __shared__ __align__(16) uint32_t ZsLoRaw[4 + 10 * ZROW];
  __shared__ __align__(16) uint32_t ZsHiRaw[4 + 10 * ZROW];
  __shared__ signed char Bqa[32 * BQSTRIDE];
  __shared__ signed char Bqb[32 * BQSTRIDE];
  __shared__ unsigned char W2hs[8 * W2STRIDE];
  __shared__ unsigned char W2ls[8 * W2STRIDE];
  __shared__ float b2s[8];

  const int tid = threadIdx.x;
  const int bb = blockIdx.y;      // batch
  const int y0 = blockIdx.x * 8;  // row-strip base
  uint32_t* const ZsLoD = ZsLoRaw + 4;
  uint32_t* const ZsHiD = ZsHiRaw + 4;

  // ---- zero pads: front 4 words + words 256..263 of each of 10 rows ------
  if (tid < 40) {  // r = tid>>2 (0..9), q = (tid>>1)&1, arr = tid&1
    int r = tid >> 2, q = (tid >> 1) & 1, arr = tid & 1;
    uint32_t* dst = (arr ? ZsHiD : ZsLoD) + r * ZROW + 256 + q * 4;
    *reinterpret_cast<uint4*>(dst) = make_uint4(0, 0, 0, 0);
  }
  if (tid == 0) {
    *reinterpret_cast<uint4*>(ZsLoRaw) = make_uint4(0, 0, 0, 0);
    *reinterpret_cast<uint4*>(ZsHiRaw) = make_uint4(0, 0, 0, 0);
  }

  // ---- vectorized pack + pre-spread: 1280 (row, half, x-quad) tasks ------
#pragma unroll
  for (int i = 0; i < 5; ++i) {
    int task = i * 256 + tid;
    int xq = task & 63;
    int hf = (task >> 6) & 1;
    int r = task >> 7;
    int y = y0 + r - 1;
    uint4 w = make_uint4(0, 0, 0, 0);
    if (y >= 0 && y < 256) {
      const float4* zp = reinterpret_cast<const float4*>(
          z + ((size_t)bb * 8 + hf * 4) * 65536 + (size_t)y * 256 + xq * 4);
      float4 v0 = zp[0];
      float4 v1 = zp[16384];
      float4 v2 = zp[32768];
      float4 v3 = zp[49152];
      w.x = spread4(v0.x, v1.x, v2.x, v3.x);
      w.y = spread4(v0.y, v1.y, v2.y, v3.y);
      w.z = spread4(v0.z, v1.z, v2.z, v3.z);
      w.w = spread4(v0.w, v1.w, v2.w, v3.w);
    }
    uint32_t* dst = (hf ? ZsHiD : ZsLoD) + r * ZROW + xq * 4;
    *reinterpret_cast<uint4*>(dst) = w;
  }

  // ---- quantize layer-1 weights: k = pidx*8 + c, p = pidx<4?pidx:pidx+1 ---
  for (int i = tid; i < 2048; i += 256) {
    int d = i & 31, k = i >> 5;
    float w;
    if (k == 63) {
      w = b1[d];
    } else {
      int pidx = k >> 3, c = k & 7;
      int p = pidx < 4 ? pidx : pidx + 1;
      w = W1[(c * 9 + p) * 32 + d];
    }
    int iw = __float2int_rn(w * 131072.0f);  // w * 2^17
    int a = __float2int_rn(w * 1024.0f);     // high part (x128)
    int b = iw - (a << 7);                   // |b| <= 64
    Bqa[d * BQSTRIDE + k] = (signed char)a;
    Bqb[d * BQSTRIDE + k] = (signed char)b;
  }
  // ---- W2 (pre-scaled by 2^-17) as [n'][d], hi/lo bf16 split; b2 ----------
  {
    int d = tid >> 3, n = tid & 7;
    float w = W2[d * 8 + n] * 7.62939453125e-6f;
    __nv_bfloat16 hi = __float2bfloat16(w);
    float hif = __bfloat162float(hi);
    __nv_bfloat16 lo = __float2bfloat16(w - hif);
    *reinterpret_cast<__nv_bfloat16*>(W2hs + n * W2STRIDE + d * 2) = hi;
    *reinterpret_cast<__nv_bfloat16*>(W2ls + n * W2STRIDE + d * 2) = lo;
    if (tid < 8) b2s[tid] = b2[tid];
  }
  __syncthreads();

  const int lane = tid & 31;
  const int warp = tid >> 5;
  const int lq = lane & 3;   // quad: k-word group / output-n group
  const int lr = lane >> 2;  // row-in-fragment group

  // ---- hoist layer-1 int8 B fragments -------------------------------------
  uint32_t bA[2][4][2], bB[2][4][2];
#pragma unroll
  for (int ks = 0; ks < 2; ++ks)
#pragma unroll
    for (int nt = 0; nt < 4; ++nt) {
      const signed char* pa = Bqa + (nt * 8 + lr) * BQSTRIDE;
      const signed char* pb = Bqb + (nt * 8 + lr) * BQSTRIDE;
      bA[ks][nt][0] = *reinterpret_cast<const uint32_t*>(pa + (lq + 8 * ks) * 4);
      bA[ks][nt][1] = *reinterpret_cast<const uint32_t*>(pa + (lq + 4 + 8 * ks) * 4);
      bB[ks][nt][0] = *reinterpret_cast<const uint32_t*>(pb + (lq + 8 * ks) * 4);
      bB[ks][nt][1] = *reinterpret_cast<const uint32_t*>(pb + (lq + 4 + 8 * ks) * 4);
    }
  uint32_t w2hf[2][2], w2lf[2][2];
#pragma unroll
  for (int ks = 0; ks < 2; ++ks) {
    const uint32_t* p = reinterpret_cast<const uint32_t*>(
        W2hs + lr * W2STRIDE + (ks * 16 + lq * 2) * 2);
    const uint32_t* q = reinterpret_cast<const uint32_t*>(
        W2ls + lr * W2STRIDE + (ks * 16 + lq * 2) * 2);
    w2hf[ks][0] = p[0];
    w2hf[ks][1] = p[4];
    w2lf[ks][0] = q[0];
    w2lf[ks][1] = q[4];
  }
  const float cb2[4] = {b2s[lq * 2], b2s[lq * 2 + 1], b2s[lq * 2],
                        b2s[lq * 2 + 1]};
  const float cz4[4] = {0.f, 0.f, 0.f, 0.f};
  const int iz4[4] = {0, 0, 0, 0};

  // lane's 4 neighbor positions; taps use (p%3 - 1) (16B-aligned layout)
  const int base_pidx = (lq >> 1) & 1;
  int oP[4];
#pragma unroll
  for (int j = 0; j < 4; ++j) {
    int pidx = base_pidx + 2 * j;
    int p = pidx < 4 ? pidx : pidx + 1;
    oP[j] = (p / 3) * ZROW + (p % 3) - 1;
  }
  const uint32_t* zarr = (lq & 1) ? ZsHiD : ZsLoD;

  float* const obase = out + (((size_t)bb * 8 + lq * 2) * 256 + y0) * 256 + lr;

  // ---- main loop: software-pipelined sp loads across tiles ----------------
  uint32_t sp1[4], sp2[4];
  {  // prologue load for the first tile (ti = warp)
    const uint32_t* zb1 = zarr + ((warp >> 4) * ZROW) + ((warp & 15) * 16) + lr;
#pragma unroll
    for (int j = 0; j < 4; ++j) {
      sp1[j] = zb1[oP[j]];
      sp2[j] = zb1[oP[j] + 8];
    }
  }

#pragma unroll 2
  for (int ti = warp; ti < 128; ti += 8) {
    const int row = ti >> 4;        // 0..7 within strip
    const int xb = (ti & 15) * 16;  // tile x base

    if (lq == 3) {  // k=63 bias lane (word 15, byte 3): force A byte to 1
      sp1[3] = __byte_perm(sp1[3], 1u, 0x4210);
      sp2[3] = __byte_perm(sp2[3], 1u, 0x4210);
    }

    // ---- layer 1: single s32 chain; pass1 A=feat*128 (u8), pass2 A=feat ---
    int acc[4][4];
    {
      uint32_t Ahi[4] = {sp1[0] << 7, sp2[0] << 7, sp1[1] << 7, sp2[1] << 7};
      uint32_t Alo[4] = {sp1[0], sp2[0], sp1[1], sp2[1]};
#pragma unroll
      for (int nt = 0; nt < 4; ++nt)
        imma16832_dc(acc[nt], Ahi, bA[0][nt], iz4);
#pragma unroll
      for (int nt = 0; nt < 4; ++nt) imma16832(acc[nt], Alo, bB[0][nt]);
    }
    {
      uint32_t Ahi[4] = {sp1[2] << 7, sp2[2] << 7, sp1[3] << 7, sp2[3] << 7};
      uint32_t Alo[4] = {sp1[2], sp2[2], sp1[3], sp2[3]};
#pragma unroll
      for (int nt = 0; nt < 4; ++nt) imma16832(acc[nt], Ahi, bA[1][nt]);
#pragma unroll
      for (int nt = 0; nt < 4; ++nt) imma16832(acc[nt], Alo, bB[1][nt]);
    }

    // ---- prefetch next tile's sp (sp regs dead after A-build) ------------
    {
      int tn = ti + 8;
      if (tn < 128) {
        const uint32_t* zb1 =
            zarr + ((tn >> 4) * ZROW) + ((tn & 15) * 16) + lr;
#pragma unroll
        for (int j = 0; j < 4; ++j) {
          sp1[j] = zb1[oP[j]];
          sp2[j] = zb1[oP[j] + 8];
        }
      }
    }

    // ---- layer 2: two chains, late operand (al) last in each chain -------
    float o1[4], o2[4];
    {
      float r0 = fmaxf(__int2float_rn(acc[0][0]), 0.f);
      float r1 = fmaxf(__int2float_rn(acc[0][1]), 0.f);
      float r2 = fmaxf(__int2float_rn(acc[0][2]), 0.f);
      float r3 = fmaxf(__int2float_rn(acc[0][3]), 0.f);
      float r4 = fmaxf(__int2float_rn(acc[1][0]), 0.f);
      float r5 = fmaxf(__int2float_rn(acc[1][1]), 0.f);
      float r6 = fmaxf(__int2float_rn(acc[1][2]), 0.f);
      float r7 = fmaxf(__int2float_rn(acc[1][3]), 0.f);
      uint32_t ah[4], al[4];
      ah[0] = pack_bf16(r0, r1);
      ah[1] = pack_bf16(r2, r3);
      ah[2] = pack_bf16(r4, r5);
      ah[3] = pack_bf16(r6, r7);
      mma16816_dc(o1, ah, w2hf[0], cb2);  // seeded with b2
      mma16816(o1, ah, w2lf[0]);          // ah-only: chain runs early
      al[0] = resid_pack(ah[0], r0, r1);
      al[1] = resid_pack(ah[1], r2, r3);
      al[2] = resid_pack(ah[2], r4, r5);
      al[3] = resid_pack(ah[3], r6, r7);
      mma16816(o1, al, w2hf[0]);          // late operand last
    }
    {
      float r0 = fmaxf(__int2float_rn(acc[2][0]), 0.f);
      float r1 = fmaxf(__int2float_rn(acc[2][1]), 0.f);
      float r2 = fmaxf(__int2float_rn(acc[2][2]), 0.f);
      float r3 = fmaxf(__int2float_rn(acc[2][3]), 0.f);
      float r4 = fmaxf(__int2float_rn(acc[3][0]), 0.f);
      float r5 = fmaxf(__int2float_rn(acc[3][1]), 0.f);
      float r6 = fmaxf(__int2float_rn(acc[3][2]), 0.f);
      float r7 = fmaxf(__int2float_rn(acc[3][3]), 0.f);
      uint32_t ah[4], al[4];
      ah[0] = pack_bf16(r0, r1);
      ah[1] = pack_bf16(r2, r3);
      ah[2] = pack_bf16(r4, r5);
      ah[3] = pack_bf16(r6, r7);
      mma16816_dc(o2, ah, w2hf[1], cz4);
      mma16816(o2, ah, w2lf[1]);
      al[0] = resid_pack(ah[0], r0, r1);
      al[1] = resid_pack(ah[1], r2, r3);
      al[2] = resid_pack(ah[2], r4, r5);
      al[3] = resid_pack(ah[3], r6, r7);
      mma16816(o2, al, w2hf[1]);
    }

    // ---- store: out[bb][n][y][x]; o1+o2 merged at store ------------------
    float* op = obase + (size_t)row * 256 + xb;
    op[0] = o1[0] + o2[0];
    op[65536] = o1[1] + o2[1];
    op[8] = o1[2] + o2[2];
    op[65536 + 8] = o1[3] + o2[3];
  }
}

extern "C" void kernel_launch(void* const* d_in, const int* in_sizes, int n_in,
                              void* d_out, int out_size) {
  (void)in_sizes;
  (void)n_in;
  (void)out_size;
  const float* z = (const float*)d_in[0];
  const float* W1 = (const float*)d_in[1];
  const float* b1 = (const float*)d_in[2];
  const float* W2 = (const float*)d_in[3];
  const float* b2 = (const float*)d_in[4];
  float* out = (float*)d_out;
  dim3 grid(32, 32);  // 32 row-strips x 32 batches
  lbp_kernel<<<grid, 256>>>(z, W1, b1, W2, b2, out);
}

// round 15
// speedup vs baseline: 1.0655x; 1.0655x over previous
#include <cuda_runtime.h>
#include <cuda_bf16.h>
#include <cstdint>

// ---------------------------------------------------------------------------
// LocalBitPredictor: per-pixel 2-layer MLP over 71 binary 3x3-neighborhood
// bits of an 8-channel binary image.
// Layer 1: int8 IMMA m16n8k32, K=64; W1 ~= 2^-17*(128*a+b), a,b s8; single
//   s32 chain (pass1 A=feat*128 u8, pass2 A=feat); D!=C zero-C first MMA.
// Layer 2: bf16 mma m16n8k16 on relu(I2F(acc)), 2^-17 folded into W2, A
//   hi/lo split; two independent chains ordered ah*w2h -> ah*w2l -> al*w2h
//   (resid strand overlaps the first two MMAs); o1 seeded with b2 via D!=C.
// R14: revert R13's prefetch machinery (regressed); keep R12 base + the two
//   zero-cost tweaks (chain reorder, PRMT bias fixup).
// ---------------------------------------------------------------------------

#define ZROW 264    // spread-word row stride (256 data + 8 zeroed pad)
#define BQSTRIDE 68 // int8 weight row stride (64 + 4 pad)
#define W2STRIDE 72 // W2 smem row stride (32 bf16 = 64B + 8 pad)

static __device__ __forceinline__ void imma16832(int* c, const uint32_t* a,
                                                 const uint32_t* b) {
  asm volatile(
      "mma.sync.aligned.m16n8k32.row.col.s32.u8.s8.s32 "
      "{%0,%1,%2,%3}, {%4,%5,%6,%7}, {%8,%9}, {%0,%1,%2,%3};"
      : "+r"(c[0]), "+r"(c[1]), "+r"(c[2]), "+r"(c[3])
      : "r"(a[0]), "r"(a[1]), "r"(a[2]), "r"(a[3]), "r"(b[0]), "r"(b[1]));
}

static __device__ __forceinline__ void imma16832_dc(int* d, const uint32_t* a,
                                                    const uint32_t* b,
                                                    const int* c) {
  asm volatile(
      "mma.sync.aligned.m16n8k32.row.col.s32.u8.s8.s32 "
      "{%0,%1,%2,%3}, {%4,%5,%6,%7}, {%8,%9}, {%10,%11,%12,%13};"
      : "=r"(d[0]), "=r"(d[1]), "=r"(d[2]), "=r"(d[3])
      : "r"(a[0]), "r"(a[1]), "r"(a[2]), "r"(a[3]), "r"(b[0]), "r"(b[1]),
        "r"(c[0]), "r"(c[1]), "r"(c[2]), "r"(c[3]));
}

static __device__ __forceinline__ void mma16816(float* c, const uint32_t* a,
                                                const uint32_t* b) {
  asm volatile(
      "mma.sync.aligned.m16n8k16.row.col.f32.bf16.bf16.f32 "
      "{%0,%1,%2,%3}, {%4,%5,%6,%7}, {%8,%9}, {%0,%1,%2,%3};"
      : "+f"(c[0]), "+f"(c[1]), "+f"(c[2]), "+f"(c[3])
      : "r"(a[0]), "r"(a[1]), "r"(a[2]), "r"(a[3]), "r"(b[0]), "r"(b[1]));
}

static __device__ __forceinline__ void mma16816_dc(float* d, const uint32_t* a,
                                                   const uint32_t* b,
                                                   const float* c) {
  asm volatile(
      "mma.sync.aligned.m16n8k16.row.col.f32.bf16.bf16.f32 "
      "{%0,%1,%2,%3}, {%4,%5,%6,%7}, {%8,%9}, {%10,%11,%12,%13};"
      : "=f"(d[0]), "=f"(d[1]), "=f"(d[2]), "=f"(d[3])
      : "r"(a[0]), "r"(a[1]), "r"(a[2]), "r"(a[3]), "r"(b[0]), "r"(b[1]),
        "f"(c[0]), "f"(c[1]), "f"(c[2]), "f"(c[3]));
}

static __device__ __forceinline__ uint32_t pack_bf16(float lo, float hi) {
  uint32_t r;
  asm("cvt.rn.bf16x2.f32 %0, %1, %2;" : "=r"(r) : "f"(hi), "f"(lo));
  return r;
}

static __device__ __forceinline__ uint32_t resid_pack(uint32_t h, float lo,
                                                      float hi) {
  float hlo = __uint_as_float(h << 16);
  float hhi = __uint_as_float(h & 0xFFFF0000u);
  return pack_bf16(lo - hlo, hi - hhi);
}

// 3-FFMA nibble dot (exact: z in {0,1}, nib <= 15) -> spread to byte lanes
static __device__ __forceinline__ uint32_t spread4(float a, float b, float c,
                                                   float d) {
  float f = fmaf(b, 2.0f, a);
  f = fmaf(c, 4.0f, f);
  f = fmaf(d, 8.0f, f);
  unsigned nib = (unsigned)f;
  return (nib * 0x00204081u) & 0x01010101u;
}

__global__ void __launch_bounds__(256, 3)
lbp_kernel(const float* __restrict__ z, const float* __restrict__ W1,
           const float* __restrict__ b1, const float* __restrict__ W2,
           const float* __restrict__ b2, float* __restrict__ out) {
  // 4-word front pad (zeroed) + 10 rows; rows 16B-aligned at data base +4
  __shared__ __align__(16) uint32_t ZsLoRaw[4 + 10 * ZROW];
  __shared__ __align__(16) uint32_t ZsHiRaw[4 + 10 * ZROW];
  __shared__ signed char Bqa[32 * BQSTRIDE];
  __shared__ signed char Bqb[32 * BQSTRIDE];
  __shared__ unsigned char W2hs[8 * W2STRIDE];
  __shared__ unsigned char W2ls[8 * W2STRIDE];
  __shared__ float b2s[8];

  const int tid = threadIdx.x;
  const int bb = blockIdx.y;      // batch
  const int y0 = blockIdx.x * 8;  // row-strip base
  uint32_t* const ZsLoD = ZsLoRaw + 4;
  uint32_t* const ZsHiD = ZsHiRaw + 4;

  // ---- zero pads: front 4 words + words 256..263 of each of 10 rows ------
  if (tid < 40) {  // r = tid>>2 (0..9), q = (tid>>1)&1, arr = tid&1
    int r = tid >> 2, q = (tid >> 1) & 1, arr = tid & 1;
    uint32_t* dst = (arr ? ZsHiD : ZsLoD) + r * ZROW + 256 + q * 4;
    *reinterpret_cast<uint4*>(dst) = make_uint4(0, 0, 0, 0);
  }
  if (tid == 0) {
    *reinterpret_cast<uint4*>(ZsLoRaw) = make_uint4(0, 0, 0, 0);
    *reinterpret_cast<uint4*>(ZsHiRaw) = make_uint4(0, 0, 0, 0);
  }

  // ---- vectorized pack + pre-spread: 1280 (row, half, x-quad) tasks ------
#pragma unroll
  for (int i = 0; i < 5; ++i) {
    int task = i * 256 + tid;
    int xq = task & 63;
    int hf = (task >> 6) & 1;
    int r = task >> 7;
    int y = y0 + r - 1;
    uint4 w = make_uint4(0, 0, 0, 0);
    if (y >= 0 && y < 256) {
      const float4* zp = reinterpret_cast<const float4*>(
          z + ((size_t)bb * 8 + hf * 4) * 65536 + (size_t)y * 256 + xq * 4);
      float4 v0 = zp[0];
      float4 v1 = zp[16384];
      float4 v2 = zp[32768];
      float4 v3 = zp[49152];
      w.x = spread4(v0.x, v1.x, v2.x, v3.x);
      w.y = spread4(v0.y, v1.y, v2.y, v3.y);
      w.z = spread4(v0.z, v1.z, v2.z, v3.z);
      w.w = spread4(v0.w, v1.w, v2.w, v3.w);
    }
    uint32_t* dst = (hf ? ZsHiD : ZsLoD) + r * ZROW + xq * 4;
    *reinterpret_cast<uint4*>(dst) = w;
  }

  // ---- quantize layer-1 weights: k = pidx*8 + c, p = pidx<4?pidx:pidx+1 ---
  for (int i = tid; i < 2048; i += 256) {
    int d = i & 31, k = i >> 5;
    float w;
    if (k == 63) {
      w = b1[d];
    } else {
      int pidx = k >> 3, c = k & 7;
      int p = pidx < 4 ? pidx : pidx + 1;
      w = W1[(c * 9 + p) * 32 + d];
    }
    int iw = __float2int_rn(w * 131072.0f);  // w * 2^17
    int a = __float2int_rn(w * 1024.0f);     // high part (x128)
    int b = iw - (a << 7);                   // |b| <= 64
    Bqa[d * BQSTRIDE + k] = (signed char)a;
    Bqb[d * BQSTRIDE + k] = (signed char)b;
  }
  // ---- W2 (pre-scaled by 2^-17) as [n'][d], hi/lo bf16 split; b2 ----------
  {
    int d = tid >> 3, n = tid & 7;
    float w = W2[d * 8 + n] * 7.62939453125e-6f;
    __nv_bfloat16 hi = __float2bfloat16(w);
    float hif = __bfloat162float(hi);
    __nv_bfloat16 lo = __float2bfloat16(w - hif);
    *reinterpret_cast<__nv_bfloat16*>(W2hs + n * W2STRIDE + d * 2) = hi;
    *reinterpret_cast<__nv_bfloat16*>(W2ls + n * W2STRIDE + d * 2) = lo;
    if (tid < 8) b2s[tid] = b2[tid];
  }
  __syncthreads();

  const int lane = tid & 31;
  const int warp = tid >> 5;
  const int lq = lane & 3;   // quad: k-word group / output-n group
  const int lr = lane >> 2;  // row-in-fragment group

  // ---- hoist layer-1 int8 B fragments -------------------------------------
  uint32_t bA[2][4][2], bB[2][4][2];
#pragma unroll
  for (int ks = 0; ks < 2; ++ks)
#pragma unroll
    for (int nt = 0; nt < 4; ++nt) {
      const signed char* pa = Bqa + (nt * 8 + lr) * BQSTRIDE;
      const signed char* pb = Bqb + (nt * 8 + lr) * BQSTRIDE;
      bA[ks][nt][0] = *reinterpret_cast<const uint32_t*>(pa + (lq + 8 * ks) * 4);
      bA[ks][nt][1] = *reinterpret_cast<const uint32_t*>(pa + (lq + 4 + 8 * ks) * 4);
      bB[ks][nt][0] = *reinterpret_cast<const uint32_t*>(pb + (lq + 8 * ks) * 4);
      bB[ks][nt][1] = *reinterpret_cast<const uint32_t*>(pb + (lq + 4 + 8 * ks) * 4);
    }
  uint32_t w2hf[2][2], w2lf[2][2];
#pragma unroll
  for (int ks = 0; ks < 2; ++ks) {
    const uint32_t* p = reinterpret_cast<const uint32_t*>(
        W2hs + lr * W2STRIDE + (ks * 16 + lq * 2) * 2);
    const uint32_t* q = reinterpret_cast<const uint32_t*>(
        W2ls + lr * W2STRIDE + (ks * 16 + lq * 2) * 2);
    w2hf[ks][0] = p[0];
    w2hf[ks][1] = p[4];
    w2lf[ks][0] = q[0];
    w2lf[ks][1] = q[4];
  }
  const float cb2[4] = {b2s[lq * 2], b2s[lq * 2 + 1], b2s[lq * 2],
                        b2s[lq * 2 + 1]};
  const float cz4[4] = {0.f, 0.f, 0.f, 0.f};
  const int iz4[4] = {0, 0, 0, 0};

  // lane's 4 neighbor positions; taps use (p%3 - 1) (16B-aligned layout)
  const int base_pidx = (lq >> 1) & 1;
  int oP[4];
#pragma unroll
  for (int j = 0; j < 4; ++j) {
    int pidx = base_pidx + 2 * j;
    int p = pidx < 4 ? pidx : pidx + 1;
    oP[j] = (p / 3) * ZROW + (p % 3) - 1;
  }
  const uint32_t* zarr = (lq & 1) ? ZsHiD : ZsLoD;

  float* const obase = out + (((size_t)bb * 8 + lq * 2) * 256 + y0) * 256 + lr;

  // ---- main loop: each warp does 16 tiles of 16 pixels --------------------
#pragma unroll 2
  for (int ti = warp; ti < 128; ti += 8) {
    const int row = ti >> 4;        // 0..7 within strip
    const int xb = (ti & 15) * 16;  // tile x base

    const uint32_t* zb1 = zarr + row * ZROW + xb + lr;
    const uint32_t* zb2 = zb1 + 8;

    uint32_t sp1[4], sp2[4];
#pragma unroll
    for (int j = 0; j < 4; ++j) {
      sp1[j] = zb1[oP[j]];
      sp2[j] = zb2[oP[j]];
    }
    if (lq == 3) {  // k=63 bias lane (word 15, byte 3): force A byte to 1
      sp1[3] = __byte_perm(sp1[3], 1u, 0x4210);
      sp2[3] = __byte_perm(sp2[3], 1u, 0x4210);
    }

    // ---- layer 1: single s32 chain; pass1 A=feat*128 (u8), pass2 A=feat ---
    int acc[4][4];
    {
      uint32_t Ahi[4] = {sp1[0] << 7, sp2[0] << 7, sp1[1] << 7, sp2[1] << 7};
      uint32_t Alo[4] = {sp1[0], sp2[0], sp1[1], sp2[1]};
#pragma unroll
      for (int nt = 0; nt < 4; ++nt)
        imma16832_dc(acc[nt], Ahi, bA[0][nt], iz4);
#pragma unroll
      for (int nt = 0; nt < 4; ++nt) imma16832(acc[nt], Alo, bB[0][nt]);
    }
    {
      uint32_t Ahi[4] = {sp1[2] << 7, sp2[2] << 7, sp1[3] << 7, sp2[3] << 7};
      uint32_t Alo[4] = {sp1[2], sp2[2], sp1[3], sp2[3]};
#pragma unroll
      for (int nt = 0; nt < 4; ++nt) imma16832(acc[nt], Ahi, bA[1][nt]);
#pragma unroll
      for (int nt = 0; nt < 4; ++nt) imma16832(acc[nt], Alo, bB[1][nt]);
    }

    // ---- layer 2: two chains; late operand (al) last in each chain -------
    float o1[4], o2[4];
    {
      float r0 = fmaxf(__int2float_rn(acc[0][0]), 0.f);
      float r1 = fmaxf(__int2float_rn(acc[0][1]), 0.f);
      float r2 = fmaxf(__int2float_rn(acc[0][2]), 0.f);
      float r3 = fmaxf(__int2float_rn(acc[0][3]), 0.f);
      float r4 = fmaxf(__int2float_rn(acc[1][0]), 0.f);
      float r5 = fmaxf(__int2float_rn(acc[1][1]), 0.f);
      float r6 = fmaxf(__int2float_rn(acc[1][2]), 0.f);
      float r7 = fmaxf(__int2float_rn(acc[1][3]), 0.f);
      uint32_t ah[4], al[4];
      ah[0] = pack_bf16(r0, r1);
      ah[1] = pack_bf16(r2, r3);
      ah[2] = pack_bf16(r4, r5);
      ah[3] = pack_bf16(r6, r7);
      mma16816_dc(o1, ah, w2hf[0], cb2);  // seeded with b2; ah ready early
      mma16816(o1, ah, w2lf[0]);
      al[0] = resid_pack(ah[0], r0, r1);  // resid overlaps the 2 MMAs above
      al[1] = resid_pack(ah[1], r2, r3);
      al[2] = resid_pack(ah[2], r4, r5);
      al[3] = resid_pack(ah[3], r6, r7);
      mma16816(o1, al, w2hf[0]);          // late operand last
    }
    {
      float r0 = fmaxf(__int2float_rn(acc[2][0]), 0.f);
      float r1 = fmaxf(__int2float_rn(acc[2][1]), 0.f);
      float r2 = fmaxf(__int2float_rn(acc[2][2]), 0.f);
      float r3 = fmaxf(__int2float_rn(acc[2][3]), 0.f);
      float r4 = fmaxf(__int2float_rn(acc[3][0]), 0.f);
      float r5 = fmaxf(__int2float_rn(acc[3][1]), 0.f);
      float r6 = fmaxf(__int2float_rn(acc[3][2]), 0.f);
      float r7 = fmaxf(__int2float_rn(acc[3][3]), 0.f);
      uint32_t ah[4], al[4];
      ah[0] = pack_bf16(r0, r1);
      ah[1] = pack_bf16(r2, r3);
      ah[2] = pack_bf16(r4, r5);
      ah[3] = pack_bf16(r6, r7);
      mma16816_dc(o2, ah, w2hf[1], cz4);
      mma16816(o2, ah, w2lf[1]);
      al[0] = resid_pack(ah[0], r0, r1);
      al[1] = resid_pack(ah[1], r2, r3);
      al[2] = resid_pack(ah[2], r4, r5);
      al[3] = resid_pack(ah[3], r6, r7);
      mma16816(o2, al, w2hf[1]);
    }

    // ---- store: out[bb][n][y][x]; o1+o2 merged at store ------------------
    float* op = obase + (size_t)row * 256 + xb;
    op[0] = o1[0] + o2[0];
    op[65536] = o1[1] + o2[1];
    op[8] = o1[2] + o2[2];
    op[65536 + 8] = o1[3] + o2[3];
  }
}

extern "C" void kernel_launch(void* const* d_in, const int* in_sizes, int n_in,
                              void* d_out, int out_size) {
  (void)in_sizes;
  (void)n_in;
  (void)out_size;
  const float* z = (const float*)d_in[0];
  const float* W1 = (const float*)d_in[1];
  const float* b1 = (const float*)d_in[2];
  const float* W2 = (const float*)d_in[3];
  const float* b2 = (const float*)d_in[4];
  float* out = (float*)d_out;
  dim3 grid(32, 32);  // 32 row-strips x 32 batches
  lbp_kernel<<<grid, 256>>>(z, W1, b1, W2, b2, out);
}

// round 17
// speedup vs baseline: 1.1105x; 1.0422x over previous
#include <cuda_runtime.h>
#include <cuda_bf16.h>
#include <cstdint>

// ---------------------------------------------------------------------------
// LocalBitPredictor: per-pixel 2-layer MLP over 71 binary 3x3-neighborhood
// bits of an 8-channel binary image.
// Layer 1: int8 IMMA m16n8k32, K=64 (k = pidx*8 + c; k=63 is the bias lane).
//   W1 quantized w ~= 2^-17 * (128*a + b), a,b in s8. Single s32 accumulator
//   chain: pass1 A-bytes = feat*128 (u8), pass2 A-bytes = feat.
//   First IMMA per n-tile uses D != C with a zero C (no acc zero-init MOVs).
// Layer 2: bf16 mma m16n8k16 on relu(I2F(acc)), 2^-17 folded into W2,
//   A hi/lo split; TWO independent 3-MMA chains; o1 seeded with b2 via D!=C.
// A-build feeds from PRE-SPREAD nibble words computed once in the prologue.
// R17: byte-identical resubmission of the session-best (R8-measured) kernel;
//   previous two attempts hit broker-layer container failures.
// ---------------------------------------------------------------------------

#define ZROW 264    // spread-word row stride (256 + halo + pad), in words
#define BQSTRIDE 68 // int8 weight row stride (64 + 4 pad)
#define W2STRIDE 72 // W2 smem row stride (32 bf16 = 64B + 8 pad)

static __device__ __forceinline__ void imma16832(int* c, const uint32_t* a,
                                                 const uint32_t* b) {
  asm volatile(
      "mma.sync.aligned.m16n8k32.row.col.s32.u8.s8.s32 "
      "{%0,%1,%2,%3}, {%4,%5,%6,%7}, {%8,%9}, {%0,%1,%2,%3};"
      : "+r"(c[0]), "+r"(c[1]), "+r"(c[2]), "+r"(c[3])
      : "r"(a[0]), "r"(a[1]), "r"(a[2]), "r"(a[3]), "r"(b[0]), "r"(b[1]));
}

// D != C form: d = a*b + c, c preserved (lets ptxas use RZ / persistent regs)
static __device__ __forceinline__ void imma16832_dc(int* d, const uint32_t* a,
                                                    const uint32_t* b,
                                                    const int* c) {
  asm volatile(
      "mma.sync.aligned.m16n8k32.row.col.s32.u8.s8.s32 "
      "{%0,%1,%2,%3}, {%4,%5,%6,%7}, {%8,%9}, {%10,%11,%12,%13};"
      : "=r"(d[0]), "=r"(d[1]), "=r"(d[2]), "=r"(d[3])
      : "r"(a[0]), "r"(a[1]), "r"(a[2]), "r"(a[3]), "r"(b[0]), "r"(b[1]),
        "r"(c[0]), "r"(c[1]), "r"(c[2]), "r"(c[3]));
}

static __device__ __forceinline__ void mma16816(float* c, const uint32_t* a,
                                                const uint32_t* b) {
  asm volatile(
      "mma.sync.aligned.m16n8k16.row.col.f32.bf16.bf16.f32 "
      "{%0,%1,%2,%3}, {%4,%5,%6,%7}, {%8,%9}, {%0,%1,%2,%3};"
      : "+f"(c[0]), "+f"(c[1]), "+f"(c[2]), "+f"(c[3])
      : "r"(a[0]), "r"(a[1]), "r"(a[2]), "r"(a[3]), "r"(b[0]), "r"(b[1]));
}

static __device__ __forceinline__ void mma16816_dc(float* d, const uint32_t* a,
                                                   const uint32_t* b,
                                                   const float* c) {
  asm volatile(
      "mma.sync.aligned.m16n8k16.row.col.f32.bf16.bf16.f32 "
      "{%0,%1,%2,%3}, {%4,%5,%6,%7}, {%8,%9}, {%10,%11,%12,%13};"
      : "=f"(d[0]), "=f"(d[1]), "=f"(d[2]), "=f"(d[3])
      : "r"(a[0]), "r"(a[1]), "r"(a[2]), "r"(a[3]), "r"(b[0]), "r"(b[1]),
        "f"(c[0]), "f"(c[1]), "f"(c[2]), "f"(c[3]));
}

static __device__ __forceinline__ uint32_t pack_bf16(float lo, float hi) {
  uint32_t r;
  asm("cvt.rn.bf16x2.f32 %0, %1, %2;" : "=r"(r) : "f"(hi), "f"(lo));
  return r;
}

static __device__ __forceinline__ uint32_t resid_pack(uint32_t h, float lo,
                                                      float hi) {
  float hlo = __uint_as_float(h << 16);
  float hhi = __uint_as_float(h & 0xFFFF0000u);
  return pack_bf16(lo - hlo, hi - hhi);
}

__global__ void __launch_bounds__(256, 3)
lbp_kernel(const float* __restrict__ z, const float* __restrict__ W1,
           const float* __restrict__ b1, const float* __restrict__ W2,
           const float* __restrict__ b2, float* __restrict__ out) {
  __shared__ uint32_t ZsLo[10 * ZROW];  // spread lo-nibble (channels 0-3)
  __shared__ uint32_t ZsHi[10 * ZROW];  // spread hi-nibble (channels 4-7)
  __shared__ signed char Bqa[32 * BQSTRIDE];
  __shared__ signed char Bqb[32 * BQSTRIDE];
  __shared__ unsigned char W2hs[8 * W2STRIDE];
  __shared__ unsigned char W2ls[8 * W2STRIDE];
  __shared__ float b2s[8];

  const int tid = threadIdx.x;
  const int bb = blockIdx.y;      // batch
  const int y0 = blockIdx.x * 8;  // row-strip base

  // ---- pack + pre-spread z: rows y0-1..y0+8, halo cols zeroed -------------
  // pack via FFMA dot with powers of two (fma pipe, exact: z in {0,1})
  {
    const int x = tid;  // 256 threads == 256 columns
#pragma unroll
    for (int r = 0; r < 10; ++r) {
      int y = y0 + r - 1;
      unsigned v = 0;
      if (y >= 0 && y < 256) {
        const float* zp = z + (size_t)bb * 8 * 65536 + (size_t)y * 256 + x;
        float f = 0.0f;
#pragma unroll
        for (int c = 0; c < 8; ++c)
          f = fmaf(zp[(size_t)c * 65536], (float)(1u << c), f);
        v = (unsigned)f;
      }
      ZsLo[r * ZROW + x + 1] = ((v & 0xFu) * 0x00204081u) & 0x01010101u;
      ZsHi[r * ZROW + x + 1] = ((v >> 4) * 0x00204081u) & 0x01010101u;
    }
    if (tid < 10) {
      ZsLo[tid * ZROW + 0] = 0;
      ZsLo[tid * ZROW + 257] = 0;
      ZsHi[tid * ZROW + 0] = 0;
      ZsHi[tid * ZROW + 257] = 0;
    }
  }

  // ---- quantize layer-1 weights: k = pidx*8 + c, p = pidx<4?pidx:pidx+1 ---
  // k==63 carries b1 (bias lane).
  for (int i = tid; i < 2048; i += 256) {
    int d = i & 31, k = i >> 5;
    float w;
    if (k == 63) {
      w = b1[d];
    } else {
      int pidx = k >> 3, c = k & 7;
      int p = pidx < 4 ? pidx : pidx + 1;
      w = W1[(c * 9 + p) * 32 + d];
    }
    int iw = __float2int_rn(w * 131072.0f);  // w * 2^17
    int a = __float2int_rn(w * 1024.0f);     // high part (x128)
    int b = iw - (a << 7);                   // |b| <= 64
    Bqa[d * BQSTRIDE + k] = (signed char)a;
    Bqb[d * BQSTRIDE + k] = (signed char)b;
  }
  // ---- W2 (pre-scaled by 2^-17) as [n'][d], hi/lo bf16 split; b2 ----------
  {
    int d = tid >> 3, n = tid & 7;
    float w = W2[d * 8 + n] * 7.62939453125e-6f;  // fold 2^-17 dequant scale
    __nv_bfloat16 hi = __float2bfloat16(w);
    float hif = __bfloat162float(hi);
    __nv_bfloat16 lo = __float2bfloat16(w - hif);
    *reinterpret_cast<__nv_bfloat16*>(W2hs + n * W2STRIDE + d * 2) = hi;
    *reinterpret_cast<__nv_bfloat16*>(W2ls + n * W2STRIDE + d * 2) = lo;
    if (tid < 8) b2s[tid] = b2[tid];
  }
  __syncthreads();

  const int lane = tid & 31;
  const int warp = tid >> 5;
  const int lq = lane & 3;   // quad: k-word group / output-n group
  const int lr = lane >> 2;  // row-in-fragment group

  // ---- hoist layer-1 int8 B fragments -------------------------------------
  uint32_t bA[2][4][2], bB[2][4][2];
#pragma unroll
  for (int ks = 0; ks < 2; ++ks)
#pragma unroll
    for (int nt = 0; nt < 4; ++nt) {
      const signed char* pa = Bqa + (nt * 8 + lr) * BQSTRIDE;
      const signed char* pb = Bqb + (nt * 8 + lr) * BQSTRIDE;
      bA[ks][nt][0] = *reinterpret_cast<const uint32_t*>(pa + (lq + 8 * ks) * 4);
      bA[ks][nt][1] = *reinterpret_cast<const uint32_t*>(pa + (lq + 4 + 8 * ks) * 4);
      bB[ks][nt][0] = *reinterpret_cast<const uint32_t*>(pb + (lq + 8 * ks) * 4);
      bB[ks][nt][1] = *reinterpret_cast<const uint32_t*>(pb + (lq + 4 + 8 * ks) * 4);
    }
  uint32_t w2hf[2][2], w2lf[2][2];
#pragma unroll
  for (int ks = 0; ks < 2; ++ks) {
    const uint32_t* p = reinterpret_cast<const uint32_t*>(
        W2hs + lr * W2STRIDE + (ks * 16 + lq * 2) * 2);
    const uint32_t* q = reinterpret_cast<const uint32_t*>(
        W2ls + lr * W2STRIDE + (ks * 16 + lq * 2) * 2);
    w2hf[ks][0] = p[0];
    w2hf[ks][1] = p[4];
    w2lf[ks][0] = q[0];
    w2lf[ks][1] = q[4];
  }
  const float cb2[4] = {b2s[lq * 2], b2s[lq * 2 + 1], b2s[lq * 2],
                        b2s[lq * 2 + 1]};
  const float cz4[4] = {0.f, 0.f, 0.f, 0.f};
  const int iz4[4] = {0, 0, 0, 0};

  // lane's 4 neighbor positions: lq<2 -> pidx {0,2,4,6}, else {1,3,5,7};
  // lq odd -> hi-nibble array (channels 4-7).
  const int base_pidx = (lq >> 1) & 1;
  int oP[4];
#pragma unroll
  for (int j = 0; j < 4; ++j) {
    int pidx = base_pidx + 2 * j;
    int p = pidx < 4 ? pidx : pidx + 1;
    oP[j] = (p / 3) * ZROW + (p % 3);
  }
  const uint32_t* zarr = (lq & 1) ? ZsHi : ZsLo;

  // base output pointer for this thread; lane owns channels n = 2lq, 2lq+1
  float* const obase = out + (((size_t)bb * 8 + lq * 2) * 256 + y0) * 256 + lr;

  // ---- main loop: each warp does 16 tiles of 16 pixels --------------------
#pragma unroll 2
  for (int ti = warp; ti < 128; ti += 8) {
    const int row = ti >> 4;        // 0..7 within strip
    const int xb = (ti & 15) * 16;  // tile x base

    const uint32_t* zb1 = zarr + row * ZROW + xb + lr;
    const uint32_t* zb2 = zb1 + 8;

    uint32_t sp1[4], sp2[4];
#pragma unroll
    for (int j = 0; j < 4; ++j) {
      sp1[j] = zb1[oP[j]];
      sp2[j] = zb2[oP[j]];
    }
    if (lq == 3) {  // k=63 bias lane (word 15, byte 3): force A byte to 1
      sp1[3] = (sp1[3] & 0x00FFFFFFu) | 0x01000000u;
      sp2[3] = (sp2[3] & 0x00FFFFFFu) | 0x01000000u;
    }

    // ---- layer 1: single s32 chain; pass1 A=feat*128 (u8), pass2 A=feat ---
    int acc[4][4];
    {
      uint32_t Ahi[4] = {sp1[0] << 7, sp2[0] << 7, sp1[1] << 7, sp2[1] << 7};
      uint32_t Alo[4] = {sp1[0], sp2[0], sp1[1], sp2[1]};
#pragma unroll
      for (int nt = 0; nt < 4; ++nt)
        imma16832_dc(acc[nt], Ahi, bA[0][nt], iz4);
#pragma unroll
      for (int nt = 0; nt < 4; ++nt) imma16832(acc[nt], Alo, bB[0][nt]);
    }
    {
      uint32_t Ahi[4] = {sp1[2] << 7, sp2[2] << 7, sp1[3] << 7, sp2[3] << 7};
      uint32_t Alo[4] = {sp1[2], sp2[2], sp1[3], sp2[3]};
#pragma unroll
      for (int nt = 0; nt < 4; ++nt) imma16832(acc[nt], Ahi, bA[1][nt]);
#pragma unroll
      for (int nt = 0; nt < 4; ++nt) imma16832(acc[nt], Alo, bB[1][nt]);
    }

    // ---- layer 2: two independent 3-MMA chains (ks=0 -> o1, ks=1 -> o2) ---
    // relu on the fma pipe: fmaxf(I2F(acc), 0)  (I2F exact, |acc| < 2^24)
    float o1[4], o2[4];
    {
      float r0 = fmaxf(__int2float_rn(acc[0][0]), 0.f);
      float r1 = fmaxf(__int2float_rn(acc[0][1]), 0.f);
      float r2 = fmaxf(__int2float_rn(acc[0][2]), 0.f);
      float r3 = fmaxf(__int2float_rn(acc[0][3]), 0.f);
      float r4 = fmaxf(__int2float_rn(acc[1][0]), 0.f);
      float r5 = fmaxf(__int2float_rn(acc[1][1]), 0.f);
      float r6 = fmaxf(__int2float_rn(acc[1][2]), 0.f);
      float r7 = fmaxf(__int2float_rn(acc[1][3]), 0.f);
      uint32_t ah[4], al[4];
      ah[0] = pack_bf16(r0, r1);
      ah[1] = pack_bf16(r2, r3);
      ah[2] = pack_bf16(r4, r5);
      ah[3] = pack_bf16(r6, r7);
      al[0] = resid_pack(ah[0], r0, r1);
      al[1] = resid_pack(ah[1], r2, r3);
      al[2] = resid_pack(ah[2], r4, r5);
      al[3] = resid_pack(ah[3], r6, r7);
      mma16816_dc(o1, ah, w2hf[0], cb2);  // seeded with b2, no init MOVs
      mma16816(o1, al, w2hf[0]);
      mma16816(o1, ah, w2lf[0]);
    }
    {
      float r0 = fmaxf(__int2float_rn(acc[2][0]), 0.f);
      float r1 = fmaxf(__int2float_rn(acc[2][1]), 0.f);
      float r2 = fmaxf(__int2float_rn(acc[2][2]), 0.f);
      float r3 = fmaxf(__int2float_rn(acc[2][3]), 0.f);
      float r4 = fmaxf(__int2float_rn(acc[3][0]), 0.f);
      float r5 = fmaxf(__int2float_rn(acc[3][1]), 0.f);
      float r6 = fmaxf(__int2float_rn(acc[3][2]), 0.f);
      float r7 = fmaxf(__int2float_rn(acc[3][3]), 0.f);
      uint32_t ah[4], al[4];
      ah[0] = pack_bf16(r0, r1);
      ah[1] = pack_bf16(r2, r3);
      ah[2] = pack_bf16(r4, r5);
      ah[3] = pack_bf16(r6, r7);
      al[0] = resid_pack(ah[0], r0, r1);
      al[1] = resid_pack(ah[1], r2, r3);
      al[2] = resid_pack(ah[2], r4, r5);
      al[3] = resid_pack(ah[3], r6, r7);
      mma16816_dc(o2, ah, w2hf[1], cz4);  // zero C, no init MOVs
      mma16816(o2, al, w2hf[1]);
      mma16816(o2, ah, w2lf[1]);
    }

    // ---- store: out[bb][n][y][x]; o1+o2 merged at store ------------------
    float* op = obase + (size_t)row * 256 + xb;
    op[0] = o1[0] + o2[0];
    op[65536] = o1[1] + o2[1];
    op[8] = o1[2] + o2[2];
    op[65536 + 8] = o1[3] + o2[3];
  }
}

extern "C" void kernel_launch(void* const* d_in, const int* in_sizes, int n_in,
                              void* d_out, int out_size) {
  (void)in_sizes;
  (void)n_in;
  (void)out_size;
  const float* z = (const float*)d_in[0];
  const float* W1 = (const float*)d_in[1];
  const float* b1 = (const float*)d_in[2];
  const float* W2 = (const float*)d_in[3];
  const float* b2 = (const float*)d_in[4];
  float* out = (float*)d_out;
  dim3 grid(32, 32);  // 32 row-strips x 32 batches
  lbp_kernel<<<grid, 256>>>(z, W1, b1, W2, b2, out);
}